// round 4
// baseline (speedup 1.0000x reference)
#include <cuda_runtime.h>
#include <math.h>

// ---------------------------------------------------------------------------
// CausalSelfAttention: x -> (QKV proj + RoPE) -> flash attention -> out proj
// B=2, T=2048, C=1024, nh=16, hs=64. All fp32.
// ---------------------------------------------------------------------------

#define NH     16
#define HS     64
#define TSEQ   2048
#define CEMB   1024
#define BROWS  4096            // B*T
#define LN1E4  9.210340371976184f

// Scratch (allocation-free): Q/K/V in (b,h,t,d) layout, y in (b,t,c) layout.
__device__ float g_q[2 * NH * TSEQ * HS];
__device__ float g_k[2 * NH * TSEQ * HS];
__device__ float g_v[2 * NH * TSEQ * HS];
__device__ float g_y[2 * TSEQ * CEMB];

// ---------------------------------------------------------------------------
// Kernel 1: QKV projection.  out[r,c] = sum_k x[r,k] * W[c,k] + b[c]
// 64x64 block tile, BK=16, 256 threads, 4x4 per thread.
// Epilogue: bias + (for Q,K) RoPE, scatter to (b,h,t,d).
// blockIdx.x = head (N tile of 64 == exactly one head), blockIdx.y = row tile,
// blockIdx.z = 0:Q 1:K 2:V.
// ---------------------------------------------------------------------------
__global__ __launch_bounds__(256) void qkv_gemm(
    const float* __restrict__ x,
    const float* __restrict__ Wq, const float* __restrict__ bq,
    const float* __restrict__ Wk, const float* __restrict__ bk,
    const float* __restrict__ Wv, const float* __restrict__ bv)
{
    const int z = blockIdx.z;
    const float* W    = (z == 0) ? Wq : (z == 1) ? Wk : Wv;
    const float* bias = (z == 0) ? bq : (z == 1) ? bk : bv;
    float* out        = (z == 0) ? g_q : (z == 1) ? g_k : g_v;

    __shared__ float As[16][68];   // [k][row], padded
    __shared__ float Bs[16][68];   // [k][col], padded

    const int tid = threadIdx.x;
    const int tx = tid & 15, ty = tid >> 4;
    const int row0 = blockIdx.y * 64;
    const int col0 = blockIdx.x * 64;

    const int lr = tid >> 2;        // 0..63 (row/col within tile)
    const int lk = (tid & 3) * 4;   // k offset 0,4,8,12

    float acc[4][4] = {};

    for (int kt = 0; kt < CEMB; kt += 16) {
        float4 a4 = *(const float4*)&x[(row0 + lr) * CEMB + kt + lk];
        float4 b4 = *(const float4*)&W[(col0 + lr) * CEMB + kt + lk];
        As[lk + 0][lr] = a4.x; As[lk + 1][lr] = a4.y;
        As[lk + 2][lr] = a4.z; As[lk + 3][lr] = a4.w;
        Bs[lk + 0][lr] = b4.x; Bs[lk + 1][lr] = b4.y;
        Bs[lk + 2][lr] = b4.z; Bs[lk + 3][lr] = b4.w;
        __syncthreads();
        #pragma unroll
        for (int kk = 0; kk < 16; kk++) {
            float4 av = *(const float4*)&As[kk][ty * 4];
            float4 bv4 = *(const float4*)&Bs[kk][tx * 4];
            float aa[4] = {av.x, av.y, av.z, av.w};
            float bb[4] = {bv4.x, bv4.y, bv4.z, bv4.w};
            #pragma unroll
            for (int i = 0; i < 4; i++)
                #pragma unroll
                for (int j = 0; j < 4; j++)
                    acc[i][j] = fmaf(aa[i], bb[j], acc[i][j]);
        }
        __syncthreads();
    }

    // Epilogue: bias, RoPE (Q,K), scatter to (b, h, t, d)
    const int h = blockIdx.x;
    const int d0 = tx * 4;
    float4 bb4 = *(const float4*)&bias[col0 + d0];

    float th0 = 0.f, th1 = 0.f;
    if (z < 2) {
        // theta_i = 10000^{-(2i)/64}; pairs at d0 -> 2i = d0, and d0+2
        th0 = expf(-((float)d0)        * (1.0f / 64.0f) * LN1E4);
        th1 = expf(-((float)(d0 + 2)) * (1.0f / 64.0f) * LN1E4);
    }

    #pragma unroll
    for (int i = 0; i < 4; i++) {
        int row = row0 + ty * 4 + i;
        int b = row >> 11;          // row / 2048
        int t = row & 2047;
        float o0 = acc[i][0] + bb4.x;
        float o1 = acc[i][1] + bb4.y;
        float o2 = acc[i][2] + bb4.z;
        float o3 = acc[i][3] + bb4.w;
        if (z < 2) {
            float c0, s0, c1, s1;
            sincosf((float)t * th0, &s0, &c0);
            sincosf((float)t * th1, &s1, &c1);
            float r0 = o0 * c0 - o1 * s0;
            float r1 = o0 * s0 + o1 * c0;
            float r2 = o2 * c1 - o3 * s1;
            float r3 = o2 * s1 + o3 * c1;
            o0 = r0; o1 = r1; o2 = r2; o3 = r3;
        }
        float4 ov = {o0, o1, o2, o3};
        *(float4*)&out[((b * NH + h) * TSEQ + t) * HS + d0] = ov;
    }
}

// ---------------------------------------------------------------------------
// Kernel 2: flash attention (fp32, causal).
// Grid: (qtile=32, bh=32). 256 threads, 4x4 microtiles.
// Per K-tile: S = Q K^T (64x64x64), online softmax, O += P V.
// ---------------------------------------------------------------------------
#define ATTN_SMEM ((64*64 + 64*68 + 64*68 + 64*64) * 4)

__global__ __launch_bounds__(256) void attn_kernel()
{
    extern __shared__ float sm[];
    float* Qs = sm;                 // [d][q]  64x64  (read: broadcast -> no pad)
    float* Ks = Qs + 64 * 64;       // [d][k]  64x68  (transposed store -> pad)
    float* Ps = Ks + 64 * 68;       // [k][q]  64x68  (transposed store -> pad)
    float* Vs = Ps + 64 * 68;       // [k][d]  64x64  (natural, float4 everywhere)

    const int tid = threadIdx.x;
    const int tx = tid & 15, ty = tid >> 4;
    const int qt = blockIdx.x;
    const int bh = blockIdx.y;

    const float* qp = g_q + (size_t)bh * TSEQ * HS;
    const float* kp = g_k + (size_t)bh * TSEQ * HS;
    const float* vp = g_v + (size_t)bh * TSEQ * HS;

    const int q0 = qt * 64;

    // Load Q tile transposed, pre-scaled by 1/sqrt(hs)
    #pragma unroll
    for (int j = 0; j < 4; j++) {
        int idx = tid + j * 256;
        int r = idx >> 4;
        int c4 = (idx & 15) * 4;
        float4 qv = *(const float4*)&qp[(q0 + r) * HS + c4];
        Qs[(c4 + 0) * 64 + r] = qv.x * 0.125f;
        Qs[(c4 + 1) * 64 + r] = qv.y * 0.125f;
        Qs[(c4 + 2) * 64 + r] = qv.z * 0.125f;
        Qs[(c4 + 3) * 64 + r] = qv.w * 0.125f;
    }

    float O[4][4] = {};
    float m[4], l[4];
    #pragma unroll
    for (int i = 0; i < 4; i++) { m[i] = -1e30f; l[i] = 0.f; }

    for (int kt = 0; kt <= qt; kt++) {
        const int k0 = kt * 64;
        __syncthreads();   // prev PV done (and Qs visible on first iter)

        // Stage K (transposed) and V (natural)
        #pragma unroll
        for (int j = 0; j < 4; j++) {
            int idx = tid + j * 256;
            int r = idx >> 4;
            int c4 = (idx & 15) * 4;
            float4 kv = *(const float4*)&kp[(k0 + r) * HS + c4];
            Ks[(c4 + 0) * 68 + r] = kv.x;
            Ks[(c4 + 1) * 68 + r] = kv.y;
            Ks[(c4 + 2) * 68 + r] = kv.z;
            Ks[(c4 + 3) * 68 + r] = kv.w;
            float4 vv = *(const float4*)&vp[(k0 + r) * HS + c4];
            *(float4*)&Vs[r * 64 + c4] = vv;
        }
        __syncthreads();

        // S = (Q * 1/8) K^T
        float s[4][4] = {};
        #pragma unroll 8
        for (int d = 0; d < 64; d++) {
            float4 a = *(const float4*)&Qs[d * 64 + ty * 4];
            float4 b = *(const float4*)&Ks[d * 68 + tx * 4];
            float aa[4] = {a.x, a.y, a.z, a.w};
            float bb[4] = {b.x, b.y, b.z, b.w};
            #pragma unroll
            for (int i = 0; i < 4; i++)
                #pragma unroll
                for (int j = 0; j < 4; j++)
                    s[i][j] = fmaf(aa[i], bb[j], s[i][j]);
        }

        // Causal mask on diagonal tile
        if (kt == qt) {
            #pragma unroll
            for (int i = 0; i < 4; i++)
                #pragma unroll
                for (int j = 0; j < 4; j++)
                    if (ty * 4 + i < tx * 4 + j) s[i][j] = -1e30f;
        }

        // Online softmax (row stats across the 16 tx lanes)
        #pragma unroll
        for (int i = 0; i < 4; i++) {
            float tm = fmaxf(fmaxf(s[i][0], s[i][1]), fmaxf(s[i][2], s[i][3]));
            #pragma unroll
            for (int off = 8; off >= 1; off >>= 1)
                tm = fmaxf(tm, __shfl_xor_sync(0xffffffffu, tm, off));
            float mn = fmaxf(m[i], tm);
            float alpha = expf(m[i] - mn);
            m[i] = mn;
            float rs = 0.f;
            #pragma unroll
            for (int j = 0; j < 4; j++) {
                s[i][j] = expf(s[i][j] - mn);
                rs += s[i][j];
            }
            #pragma unroll
            for (int off = 8; off >= 1; off >>= 1)
                rs += __shfl_xor_sync(0xffffffffu, rs, off);
            l[i] = l[i] * alpha + rs;
            #pragma unroll
            for (int j = 0; j < 4; j++) O[i][j] *= alpha;
        }

        // Store P transposed [k][q]
        #pragma unroll
        for (int i = 0; i < 4; i++)
            #pragma unroll
            for (int j = 0; j < 4; j++)
                Ps[(tx * 4 + j) * 68 + (ty * 4 + i)] = s[i][j];
        __syncthreads();

        // O += P V
        #pragma unroll 8
        for (int kk = 0; kk < 64; kk++) {
            float4 pv = *(const float4*)&Ps[kk * 68 + ty * 4];
            float4 vv = *(const float4*)&Vs[kk * 64 + tx * 4];
            float pp[4] = {pv.x, pv.y, pv.z, pv.w};
            float vb[4] = {vv.x, vv.y, vv.z, vv.w};
            #pragma unroll
            for (int i = 0; i < 4; i++)
                #pragma unroll
                for (int j = 0; j < 4; j++)
                    O[i][j] = fmaf(pp[i], vb[j], O[i][j]);
        }
    }

    // Normalize, write y in (b, t, c) layout for the output projection
    const int b = bh >> 4, h = bh & 15;
    #pragma unroll
    for (int i = 0; i < 4; i++) {
        float inv = 1.0f / l[i];
        int trow = q0 + ty * 4 + i;
        float4 ov = {O[i][0] * inv, O[i][1] * inv, O[i][2] * inv, O[i][3] * inv};
        *(float4*)&g_y[((size_t)b * TSEQ + trow) * CEMB + h * HS + tx * 4] = ov;
    }
}

// ---------------------------------------------------------------------------
// Kernel 3: output projection. out[r,c] = sum_k y[r,k] * Wp[c,k] + bp[c]
// ---------------------------------------------------------------------------
__global__ __launch_bounds__(256) void proj_gemm(
    const float* __restrict__ Wp, const float* __restrict__ bp,
    float* __restrict__ out)
{
    __shared__ float As[16][68];
    __shared__ float Bs[16][68];

    const int tid = threadIdx.x;
    const int tx = tid & 15, ty = tid >> 4;
    const int row0 = blockIdx.y * 64;
    const int col0 = blockIdx.x * 64;

    const int lr = tid >> 2;
    const int lk = (tid & 3) * 4;

    float acc[4][4] = {};

    for (int kt = 0; kt < CEMB; kt += 16) {
        float4 a4 = *(const float4*)&g_y[(row0 + lr) * CEMB + kt + lk];
        float4 b4 = *(const float4*)&Wp[(col0 + lr) * CEMB + kt + lk];
        As[lk + 0][lr] = a4.x; As[lk + 1][lr] = a4.y;
        As[lk + 2][lr] = a4.z; As[lk + 3][lr] = a4.w;
        Bs[lk + 0][lr] = b4.x; Bs[lk + 1][lr] = b4.y;
        Bs[lk + 2][lr] = b4.z; Bs[lk + 3][lr] = b4.w;
        __syncthreads();
        #pragma unroll
        for (int kk = 0; kk < 16; kk++) {
            float4 av = *(const float4*)&As[kk][ty * 4];
            float4 bv4 = *(const float4*)&Bs[kk][tx * 4];
            float aa[4] = {av.x, av.y, av.z, av.w};
            float bb[4] = {bv4.x, bv4.y, bv4.z, bv4.w};
            #pragma unroll
            for (int i = 0; i < 4; i++)
                #pragma unroll
                for (int j = 0; j < 4; j++)
                    acc[i][j] = fmaf(aa[i], bb[j], acc[i][j]);
        }
        __syncthreads();
    }

    float4 bb4 = *(const float4*)&bp[col0 + tx * 4];
    #pragma unroll
    for (int i = 0; i < 4; i++) {
        int row = row0 + ty * 4 + i;
        float4 ov = {acc[i][0] + bb4.x, acc[i][1] + bb4.y,
                     acc[i][2] + bb4.z, acc[i][3] + bb4.w};
        *(float4*)&out[(size_t)row * CEMB + col0 + tx * 4] = ov;
    }
}

// ---------------------------------------------------------------------------
extern "C" void kernel_launch(void* const* d_in, const int* in_sizes, int n_in,
                              void* d_out, int out_size)
{
    const float* x  = (const float*)d_in[0];
    const float* Wq = (const float*)d_in[1];
    const float* bq = (const float*)d_in[2];
    const float* Wk = (const float*)d_in[3];
    const float* bk = (const float*)d_in[4];
    const float* Wv = (const float*)d_in[5];
    const float* bv = (const float*)d_in[6];
    const float* Wp = (const float*)d_in[7];
    const float* bp = (const float*)d_in[8];
    float* out = (float*)d_out;

    cudaFuncSetAttribute(attn_kernel,
                         cudaFuncAttributeMaxDynamicSharedMemorySize, ATTN_SMEM);

    qkv_gemm<<<dim3(NH, BROWS / 64, 3), 256>>>(x, Wq, bq, Wk, bk, Wv, bv);
    attn_kernel<<<dim3(TSEQ / 64, 2 * NH), 256, ATTN_SMEM>>>();
    proj_gemm<<<dim3(NH, BROWS / 64), 256>>>(Wp, bp, out);
}

// round 5
// speedup vs baseline: 1.2988x; 1.2988x over previous
#include <cuda_runtime.h>
#include <math.h>

// ---------------------------------------------------------------------------
// CausalSelfAttention: x -> (QKV proj + RoPE) -> flash attention -> out proj
// B=2, T=2048, C=1024, nh=16, hs=64. fp32 with packed f32x2 (FFMA2) math.
// ---------------------------------------------------------------------------

#define NH     16
#define HS     64
#define TSEQ   2048
#define CEMB   1024
#define BROWS  4096
#define LN1E4  9.210340371976184f
#define ASTR   132     // GEMM smem row stride (floats), 16B-aligned rows
#define QSTR   132     // attn Q/P smem row stride
#define KSTR   68      // attn K/V smem row stride

typedef unsigned long long u64;

// ---- packed f32x2 helpers (sm_100+ PTX) -----------------------------------
__device__ __forceinline__ void fma2(u64& c, u64 a, u64 b) {
    asm("fma.rn.f32x2 %0, %1, %2, %0;" : "+l"(c) : "l"(a), "l"(b));
}
__device__ __forceinline__ void mul2(u64& c, u64 a) {
    asm("mul.rn.f32x2 %0, %0, %1;" : "+l"(c) : "l"(a));
}
__device__ __forceinline__ u64 bc2(float v) {
    u64 r; asm("mov.b64 %0, {%1, %1};" : "=l"(r) : "f"(v)); return r;
}
__device__ __forceinline__ u64 pk2(float lo, float hi) {
    u64 r; asm("mov.b64 %0, {%1, %2};" : "=l"(r) : "f"(lo), "f"(hi)); return r;
}
__device__ __forceinline__ float2 up2(u64 v) {
    float2 f; asm("mov.b64 {%0, %1}, %2;" : "=f"(f.x), "=f"(f.y) : "l"(v)); return f;
}

// Scratch (allocation-free): Q/K/V in (b,h,t,d) layout, y in (b,t,c) layout.
__device__ __align__(16) float g_q[2 * NH * TSEQ * HS];
__device__ __align__(16) float g_k[2 * NH * TSEQ * HS];
__device__ __align__(16) float g_v[2 * NH * TSEQ * HS];
__device__ __align__(16) float g_y[2 * TSEQ * CEMB];

// ---------------------------------------------------------------------------
// Kernel 1: QKV projection.  out[r,c] = sum_k x[r,k] * W[c,k] + b[c]
// 128x128 block tile, BK=16, 256 threads, 8x8 microtile, FFMA2 accumulators
// packed over row pairs. Epilogue: bias + RoPE (Q,K), scatter to (b,h,t,d).
// blockIdx.x = pair of heads (128 cols = 2 heads), blockIdx.y = row tile,
// blockIdx.z = 0:Q 1:K 2:V.
// ---------------------------------------------------------------------------
__global__ __launch_bounds__(256, 2) void qkv_gemm(
    const float* __restrict__ x,
    const float* __restrict__ Wq, const float* __restrict__ bq,
    const float* __restrict__ Wk, const float* __restrict__ bk,
    const float* __restrict__ Wv, const float* __restrict__ bv)
{
    const int z = blockIdx.z;
    const float* W    = (z == 0) ? Wq : (z == 1) ? Wk : Wv;
    const float* bias = (z == 0) ? bq : (z == 1) ? bk : bv;
    float* out        = (z == 0) ? g_q : (z == 1) ? g_k : g_v;

    __shared__ __align__(16) float As[16 * ASTR];   // [k][m] transposed
    __shared__ __align__(16) float Bs[16 * ASTR];   // [k][n] transposed

    const int tid = threadIdx.x;
    const int tx = tid & 15, ty = tid >> 4;
    const int row0 = blockIdx.y * 128;
    const int col0 = blockIdx.x * 128;

    const int rs_ = tid >> 1;           // 0..127: staging row
    const int ks_ = (tid & 1) * 8;      // staging k offset

    const float* ap = x + (size_t)(row0 + rs_) * CEMB + ks_;
    const float* bp = W + (size_t)(col0 + rs_) * CEMB + ks_;

    u64 acc[4][8];                      // [row-pair][col], packed f32x2
    #pragma unroll
    for (int p = 0; p < 4; p++)
        #pragma unroll
        for (int j = 0; j < 8; j++) acc[p][j] = 0ULL;

    float4 pa0 = *(const float4*)(ap);
    float4 pa1 = *(const float4*)(ap + 4);
    float4 pb0 = *(const float4*)(bp);
    float4 pb1 = *(const float4*)(bp + 4);

    for (int kt = 0; kt < CEMB; kt += 16) {
        __syncthreads();
        As[(ks_ + 0) * ASTR + rs_] = pa0.x;
        As[(ks_ + 1) * ASTR + rs_] = pa0.y;
        As[(ks_ + 2) * ASTR + rs_] = pa0.z;
        As[(ks_ + 3) * ASTR + rs_] = pa0.w;
        As[(ks_ + 4) * ASTR + rs_] = pa1.x;
        As[(ks_ + 5) * ASTR + rs_] = pa1.y;
        As[(ks_ + 6) * ASTR + rs_] = pa1.z;
        As[(ks_ + 7) * ASTR + rs_] = pa1.w;
        Bs[(ks_ + 0) * ASTR + rs_] = pb0.x;
        Bs[(ks_ + 1) * ASTR + rs_] = pb0.y;
        Bs[(ks_ + 2) * ASTR + rs_] = pb0.z;
        Bs[(ks_ + 3) * ASTR + rs_] = pb0.w;
        Bs[(ks_ + 4) * ASTR + rs_] = pb1.x;
        Bs[(ks_ + 5) * ASTR + rs_] = pb1.y;
        Bs[(ks_ + 6) * ASTR + rs_] = pb1.z;
        Bs[(ks_ + 7) * ASTR + rs_] = pb1.w;
        __syncthreads();
        if (kt + 16 < CEMB) {           // prefetch next tile under compute
            pa0 = *(const float4*)(ap + kt + 16);
            pa1 = *(const float4*)(ap + kt + 20);
            pb0 = *(const float4*)(bp + kt + 16);
            pb1 = *(const float4*)(bp + kt + 20);
        }
        #pragma unroll
        for (int kk = 0; kk < 16; kk++) {
            const float* abase = &As[kk * ASTR + ty * 4];
            ulonglong2 aA = *(const ulonglong2*)abase;        // rows ty*4+0..3
            ulonglong2 aB = *(const ulonglong2*)(abase + 64); // rows 64+ty*4+0..3
            const float* bbase = &Bs[kk * ASTR + tx * 4];
            float4 b0 = *(const float4*)bbase;                // cols tx*4+0..3
            float4 b1 = *(const float4*)(bbase + 64);         // cols 64+tx*4+0..3
            u64 aa[4] = {aA.x, aA.y, aB.x, aB.y};
            u64 bb[8] = {bc2(b0.x), bc2(b0.y), bc2(b0.z), bc2(b0.w),
                         bc2(b1.x), bc2(b1.y), bc2(b1.z), bc2(b1.w)};
            #pragma unroll
            for (int p = 0; p < 4; p++)
                #pragma unroll
                for (int j = 0; j < 8; j++)
                    fma2(acc[p][j], aa[p], bb[j]);
        }
    }

    // Epilogue: bias, RoPE (Q,K), scatter to (b, h, t, d).
    float4 bb0 = *(const float4*)&bias[col0 + tx * 4];
    float4 bb1 = *(const float4*)&bias[col0 + 64 + tx * 4];
    float bvv[8] = {bb0.x, bb0.y, bb0.z, bb0.w, bb1.x, bb1.y, bb1.z, bb1.w};

    const int d0 = tx * 4;              // d within head (same for both heads)
    const int h0 = blockIdx.x * 2;
    float th0 = 0.f, th1 = 0.f;
    if (z < 2) {
        th0 = expf(-((float)d0)       * (LN1E4 / 64.0f));
        th1 = expf(-((float)(d0 + 2)) * (LN1E4 / 64.0f));
    }

    #pragma unroll
    for (int p = 0; p < 4; p++) {
        #pragma unroll
        for (int e = 0; e < 2; e++) {
            float v[8];
            #pragma unroll
            for (int j = 0; j < 8; j++) {
                float2 f = up2(acc[p][j]);
                v[j] = ((e == 0) ? f.x : f.y) + bvv[j];
            }
            int rl = ((p >> 1) << 6) + ty * 4 + ((p & 1) << 1) + e;
            int row = row0 + rl;
            int b = row >> 11;
            int t = row & 2047;
            if (z < 2) {
                float c0, s0, c1, s1;
                sincosf((float)t * th0, &s0, &c0);
                sincosf((float)t * th1, &s1, &c1);
                float r0 = v[0] * c0 - v[1] * s0, r1 = v[0] * s0 + v[1] * c0;
                float r2 = v[2] * c1 - v[3] * s1, r3 = v[2] * s1 + v[3] * c1;
                float r4 = v[4] * c0 - v[5] * s0, r5 = v[4] * s0 + v[5] * c0;
                float r6 = v[6] * c1 - v[7] * s1, r7 = v[6] * s1 + v[7] * c1;
                v[0] = r0; v[1] = r1; v[2] = r2; v[3] = r3;
                v[4] = r4; v[5] = r5; v[6] = r6; v[7] = r7;
            }
            float4 o0 = {v[0], v[1], v[2], v[3]};
            float4 o1 = {v[4], v[5], v[6], v[7]};
            *(float4*)&out[(((size_t)b * NH + h0) * TSEQ + t) * HS + d0] = o0;
            *(float4*)&out[(((size_t)b * NH + h0 + 1) * TSEQ + t) * HS + d0] = o1;
        }
    }
}

// ---------------------------------------------------------------------------
// Kernel 2: flash attention (fp32/FFMA2, causal).
// Br=128 q-rows, Bc=64 keys. 256 threads, 8q x 4k microtile, row-pair FFMA2.
// Heavy q-tiles scheduled first (reversed blockIdx.x).
// ---------------------------------------------------------------------------
#define ATTN_SMEM ((64 * QSTR * 2 + 64 * KSTR * 2) * 4)   // 102400 bytes

__global__ __launch_bounds__(256) void attn_kernel()
{
    extern __shared__ __align__(16) float sm[];
    float* Qs = sm;                  // [d][q]  64 x 132, pre-scaled
    float* Ks = Qs + 64 * QSTR;      // [d][k]  64 x 68
    float* Ps = Ks + 64 * KSTR;      // [k][q]  64 x 132
    float* Vs = Ps + 64 * QSTR;      // [k][d]  64 x 68

    const int tid = threadIdx.x;
    const int tx = tid & 15, ty = tid >> 4;
    const int qt = (gridDim.x - 1) - blockIdx.x;    // heavy tiles first
    const int bh = blockIdx.y;

    const float* qp = g_q + (size_t)bh * TSEQ * HS;
    const float* kp = g_k + (size_t)bh * TSEQ * HS;
    const float* vp = g_v + (size_t)bh * TSEQ * HS;

    const int q0 = qt * 128;

    // Load Q tile transposed, pre-scaled by 1/sqrt(hs)
    #pragma unroll
    for (int jj = 0; jj < 8; jj++) {
        int idx = tid + jj * 256;
        int r = idx >> 4;
        int c4 = (idx & 15) * 4;
        float4 qv = *(const float4*)&qp[(size_t)(q0 + r) * HS + c4];
        Qs[(c4 + 0) * QSTR + r] = qv.x * 0.125f;
        Qs[(c4 + 1) * QSTR + r] = qv.y * 0.125f;
        Qs[(c4 + 2) * QSTR + r] = qv.z * 0.125f;
        Qs[(c4 + 3) * QSTR + r] = qv.w * 0.125f;
    }

    u64 O[4][4];                     // [row-pair][d-col], packed f32x2
    #pragma unroll
    for (int p = 0; p < 4; p++)
        #pragma unroll
        for (int j = 0; j < 4; j++) O[p][j] = 0ULL;
    float m[8], l[8];
    #pragma unroll
    for (int i = 0; i < 8; i++) { m[i] = -1e30f; l[i] = 0.f; }

    const int ktmax = 2 * qt + 1;
    for (int kt = 0; kt <= ktmax; kt++) {
        const int k0 = kt * 64;
        __syncthreads();             // prev PV done reading Ps/Vs; Qs ready
        #pragma unroll
        for (int jj = 0; jj < 4; jj++) {
            int idx = tid + jj * 256;
            int r = idx >> 4;
            int c4 = (idx & 15) * 4;
            float4 kv = *(const float4*)&kp[(size_t)(k0 + r) * HS + c4];
            Ks[(c4 + 0) * KSTR + r] = kv.x;
            Ks[(c4 + 1) * KSTR + r] = kv.y;
            Ks[(c4 + 2) * KSTR + r] = kv.z;
            Ks[(c4 + 3) * KSTR + r] = kv.w;
            float4 vv = *(const float4*)&vp[(size_t)(k0 + r) * HS + c4];
            *(float4*)&Vs[r * KSTR + c4] = vv;
        }
        __syncthreads();

        // S = (Q/8) K^T  -> packed over row pairs
        u64 s2[4][4];
        #pragma unroll
        for (int p = 0; p < 4; p++)
            #pragma unroll
            for (int j = 0; j < 4; j++) s2[p][j] = 0ULL;
        #pragma unroll 8
        for (int d = 0; d < 64; d++) {
            const float* qb = &Qs[d * QSTR + ty * 4];
            ulonglong2 aA = *(const ulonglong2*)qb;
            ulonglong2 aB = *(const ulonglong2*)(qb + 64);
            float4 kv = *(const float4*)&Ks[d * KSTR + tx * 4];
            u64 aa[4] = {aA.x, aA.y, aB.x, aB.y};
            u64 bb[4] = {bc2(kv.x), bc2(kv.y), bc2(kv.z), bc2(kv.w)};
            #pragma unroll
            for (int p = 0; p < 4; p++)
                #pragma unroll
                for (int j = 0; j < 4; j++)
                    fma2(s2[p][j], aa[p], bb[j]);
        }

        // Unpack to scalars for mask + softmax (row slot i=2p+e)
        float sf[8][4];
        #pragma unroll
        for (int p = 0; p < 4; p++)
            #pragma unroll
            for (int j = 0; j < 4; j++) {
                float2 f = up2(s2[p][j]);
                sf[2 * p][j] = f.x;
                sf[2 * p + 1][j] = f.y;
            }

        if (kt >= 2 * qt) {          // only last two tiles touch the diagonal
            #pragma unroll
            for (int i = 0; i < 8; i++) {
                int r = q0 + ((i >> 2) << 6) + ty * 4 + (i & 3);
                #pragma unroll
                for (int j = 0; j < 4; j++)
                    if (k0 + tx * 4 + j > r) sf[i][j] = -1e30f;
            }
        }

        // Online softmax (row stats across the 16 tx lanes)
        float alpha[8];
        #pragma unroll
        for (int i = 0; i < 8; i++) {
            float tm = fmaxf(fmaxf(sf[i][0], sf[i][1]), fmaxf(sf[i][2], sf[i][3]));
            #pragma unroll
            for (int off = 8; off >= 1; off >>= 1)
                tm = fmaxf(tm, __shfl_xor_sync(0xffffffffu, tm, off));
            float mn = fmaxf(m[i], tm);
            alpha[i] = __expf(m[i] - mn);
            m[i] = mn;
            float rs = 0.f;
            #pragma unroll
            for (int j = 0; j < 4; j++) {
                sf[i][j] = __expf(sf[i][j] - mn);
                rs += sf[i][j];
            }
            #pragma unroll
            for (int off = 8; off >= 1; off >>= 1)
                rs += __shfl_xor_sync(0xffffffffu, rs, off);
            l[i] = l[i] * alpha[i] + rs;
        }

        // Rescale O by per-row alpha (packed pairwise)
        #pragma unroll
        for (int p = 0; p < 4; p++) {
            u64 apk = pk2(alpha[2 * p], alpha[2 * p + 1]);
            #pragma unroll
            for (int j = 0; j < 4; j++) mul2(O[p][j], apk);
        }

        // Store P transposed [k][q]
        #pragma unroll
        for (int i = 0; i < 8; i++) {
            int rl = ((i >> 2) << 6) + ty * 4 + (i & 3);
            #pragma unroll
            for (int j = 0; j < 4; j++)
                Ps[(tx * 4 + j) * QSTR + rl] = sf[i][j];
        }
        __syncthreads();

        // O += P V
        #pragma unroll 8
        for (int kk = 0; kk < 64; kk++) {
            const float* pb = &Ps[kk * QSTR + ty * 4];
            ulonglong2 aA = *(const ulonglong2*)pb;
            ulonglong2 aB = *(const ulonglong2*)(pb + 64);
            float4 vv = *(const float4*)&Vs[kk * KSTR + tx * 4];
            u64 aa[4] = {aA.x, aA.y, aB.x, aB.y};
            u64 bb[4] = {bc2(vv.x), bc2(vv.y), bc2(vv.z), bc2(vv.w)};
            #pragma unroll
            for (int p = 0; p < 4; p++)
                #pragma unroll
                for (int j = 0; j < 4; j++)
                    fma2(O[p][j], aa[p], bb[j]);
        }
    }

    // Normalize, write y in (b, t, c) layout for the output projection
    const int b = bh >> 4, h = bh & 15;
    #pragma unroll
    for (int p = 0; p < 4; p++) {
        float2 f0 = up2(O[p][0]);
        float2 f1 = up2(O[p][1]);
        float2 f2 = up2(O[p][2]);
        float2 f3 = up2(O[p][3]);
        int i0 = 2 * p;
        float inv0 = 1.0f / l[i0];
        float inv1 = 1.0f / l[i0 + 1];
        int t0 = q0 + ((i0 >> 2) << 6) + ty * 4 + (i0 & 3);
        float4 o0 = {f0.x * inv0, f1.x * inv0, f2.x * inv0, f3.x * inv0};
        float4 o1 = {f0.y * inv1, f1.y * inv1, f2.y * inv1, f3.y * inv1};
        *(float4*)&g_y[((size_t)b * TSEQ + t0) * CEMB + h * HS + tx * 4] = o0;
        *(float4*)&g_y[((size_t)b * TSEQ + t0 + 1) * CEMB + h * HS + tx * 4] = o1;
    }
}

// ---------------------------------------------------------------------------
// Kernel 3: output projection. out[r,c] = sum_k y[r,k] * Wp[c,k] + bp[c]
// Same 128x128 FFMA2 GEMM as kernel 1, plain bias epilogue.
// ---------------------------------------------------------------------------
__global__ __launch_bounds__(256, 2) void proj_gemm(
    const float* __restrict__ Wp, const float* __restrict__ bp,
    float* __restrict__ out)
{
    __shared__ __align__(16) float As[16 * ASTR];
    __shared__ __align__(16) float Bs[16 * ASTR];

    const int tid = threadIdx.x;
    const int tx = tid & 15, ty = tid >> 4;
    const int row0 = blockIdx.y * 128;
    const int col0 = blockIdx.x * 128;

    const int rs_ = tid >> 1;
    const int ks_ = (tid & 1) * 8;

    const float* ap = g_y + (size_t)(row0 + rs_) * CEMB + ks_;
    const float* bpW = Wp + (size_t)(col0 + rs_) * CEMB + ks_;

    u64 acc[4][8];
    #pragma unroll
    for (int p = 0; p < 4; p++)
        #pragma unroll
        for (int j = 0; j < 8; j++) acc[p][j] = 0ULL;

    float4 pa0 = *(const float4*)(ap);
    float4 pa1 = *(const float4*)(ap + 4);
    float4 pb0 = *(const float4*)(bpW);
    float4 pb1 = *(const float4*)(bpW + 4);

    for (int kt = 0; kt < CEMB; kt += 16) {
        __syncthreads();
        As[(ks_ + 0) * ASTR + rs_] = pa0.x;
        As[(ks_ + 1) * ASTR + rs_] = pa0.y;
        As[(ks_ + 2) * ASTR + rs_] = pa0.z;
        As[(ks_ + 3) * ASTR + rs_] = pa0.w;
        As[(ks_ + 4) * ASTR + rs_] = pa1.x;
        As[(ks_ + 5) * ASTR + rs_] = pa1.y;
        As[(ks_ + 6) * ASTR + rs_] = pa1.z;
        As[(ks_ + 7) * ASTR + rs_] = pa1.w;
        Bs[(ks_ + 0) * ASTR + rs_] = pb0.x;
        Bs[(ks_ + 1) * ASTR + rs_] = pb0.y;
        Bs[(ks_ + 2) * ASTR + rs_] = pb0.z;
        Bs[(ks_ + 3) * ASTR + rs_] = pb0.w;
        Bs[(ks_ + 4) * ASTR + rs_] = pb1.x;
        Bs[(ks_ + 5) * ASTR + rs_] = pb1.y;
        Bs[(ks_ + 6) * ASTR + rs_] = pb1.z;
        Bs[(ks_ + 7) * ASTR + rs_] = pb1.w;
        __syncthreads();
        if (kt + 16 < CEMB) {
            pa0 = *(const float4*)(ap + kt + 16);
            pa1 = *(const float4*)(ap + kt + 20);
            pb0 = *(const float4*)(bpW + kt + 16);
            pb1 = *(const float4*)(bpW + kt + 20);
        }
        #pragma unroll
        for (int kk = 0; kk < 16; kk++) {
            const float* abase = &As[kk * ASTR + ty * 4];
            ulonglong2 aA = *(const ulonglong2*)abase;
            ulonglong2 aB = *(const ulonglong2*)(abase + 64);
            const float* bbase = &Bs[kk * ASTR + tx * 4];
            float4 b0 = *(const float4*)bbase;
            float4 b1 = *(const float4*)(bbase + 64);
            u64 aa[4] = {aA.x, aA.y, aB.x, aB.y};
            u64 bb[8] = {bc2(b0.x), bc2(b0.y), bc2(b0.z), bc2(b0.w),
                         bc2(b1.x), bc2(b1.y), bc2(b1.z), bc2(b1.w)};
            #pragma unroll
            for (int p = 0; p < 4; p++)
                #pragma unroll
                for (int j = 0; j < 8; j++)
                    fma2(acc[p][j], aa[p], bb[j]);
        }
    }

    float4 bb0 = *(const float4*)&bp[col0 + tx * 4];
    float4 bb1 = *(const float4*)&bp[col0 + 64 + tx * 4];
    float bvv[8] = {bb0.x, bb0.y, bb0.z, bb0.w, bb1.x, bb1.y, bb1.z, bb1.w};

    #pragma unroll
    for (int p = 0; p < 4; p++) {
        #pragma unroll
        for (int e = 0; e < 2; e++) {
            float v[8];
            #pragma unroll
            for (int j = 0; j < 8; j++) {
                float2 f = up2(acc[p][j]);
                v[j] = ((e == 0) ? f.x : f.y) + bvv[j];
            }
            int rl = ((p >> 1) << 6) + ty * 4 + ((p & 1) << 1) + e;
            size_t row = (size_t)(row0 + rl);
            float4 o0 = {v[0], v[1], v[2], v[3]};
            float4 o1 = {v[4], v[5], v[6], v[7]};
            *(float4*)&out[row * CEMB + col0 + tx * 4] = o0;
            *(float4*)&out[row * CEMB + col0 + 64 + tx * 4] = o1;
        }
    }
}

// ---------------------------------------------------------------------------
extern "C" void kernel_launch(void* const* d_in, const int* in_sizes, int n_in,
                              void* d_out, int out_size)
{
    const float* x  = (const float*)d_in[0];
    const float* Wq = (const float*)d_in[1];
    const float* bq = (const float*)d_in[2];
    const float* Wk = (const float*)d_in[3];
    const float* bk = (const float*)d_in[4];
    const float* Wv = (const float*)d_in[5];
    const float* bv = (const float*)d_in[6];
    const float* Wp = (const float*)d_in[7];
    const float* bp = (const float*)d_in[8];
    float* out = (float*)d_out;

    cudaFuncSetAttribute(attn_kernel,
                         cudaFuncAttributeMaxDynamicSharedMemorySize, ATTN_SMEM);

    qkv_gemm<<<dim3(CEMB / 128, BROWS / 128, 3), 256>>>(x, Wq, bq, Wk, bk, Wv, bv);
    attn_kernel<<<dim3(TSEQ / 128, 2 * NH), 256, ATTN_SMEM>>>();
    proj_gemm<<<dim3(CEMB / 128, BROWS / 128), 256>>>(Wp, bp, out);
}